// round 14
// baseline (speedup 1.0000x reference)
#include <cuda_runtime.h>
#include <math.h>

#define NN 100000
#define EE 1280000
#define DIN 64
#define DOUT 64
#define DEDGE 16
#define NEG 0.01f

#define SCAN_T 512
#define SCAN_BLOCKS ((NN + SCAN_T - 1) / SCAN_T)   // 196

#define TM 128                                     // nodes per k_node block
#define NODE_BLOCKS ((NN + TM - 1) / TM)           // 782

typedef unsigned long long ull;

// ---------------- device scratch (static, no allocation) ----------------
__device__ float  g_xt[NN * DOUT];      // x @ W2^T, natural [n][d]
__device__ float  g_sf[NN * DOUT];      // x @ W1a^T, natural [n][d]
__device__ float  g_rdot[NN];
__device__ float2 g_ls[EE];             // CSR-ordered {logit, src-as-bits}
__device__ int    g_count[NN];
__device__ int    g_rowptr[NN + 1];
__device__ int    g_wptr[NN];
__device__ int    g_bsum[SCAN_BLOCKS];

__device__ __forceinline__ float leaky(float v) {
    return fmaxf(v, NEG * v);
}
__device__ __forceinline__ float warp_sum(float v) {
    #pragma unroll
    for (int o = 16; o > 0; o >>= 1) v += __shfl_xor_sync(0xFFFFFFFFu, v, o);
    return v;
}
__device__ __forceinline__ float warp_max(float v) {
    #pragma unroll
    for (int o = 16; o > 0; o >>= 1) v = fmaxf(v, __shfl_xor_sync(0xFFFFFFFFu, v, o));
    return v;
}

// packed f32x2 helpers
__device__ __forceinline__ ull packf2(float lo, float hi) {
    ull r;
    asm("mov.b64 %0, {%1, %2};" : "=l"(r) : "f"(lo), "f"(hi));
    return r;
}
__device__ __forceinline__ void unpackf2(ull v, float& lo, float& hi) {
    asm("mov.b64 {%0, %1}, %2;" : "=f"(lo), "=f"(hi) : "l"(v));
}
__device__ __forceinline__ void ffma2(ull& acc, ull a, ull b) {
    asm("fma.rn.f32x2 %0, %1, %2, %0;" : "+l"(acc) : "l"(a), "l"(b));
}

// ---------------- Kh: dst histogram (4 edges/thread) ----------------
__global__ __launch_bounds__(256) void k_hist(const int* __restrict__ dst) {
    int t = blockIdx.x * blockDim.x + threadIdx.x;
    if (t * 4 < EE) {
        int4 d4 = ((const int4*)dst)[t];
        atomicAdd(&g_count[d4.x], 1);
        atomicAdd(&g_count[d4.y], 1);
        atomicAdd(&g_count[d4.z], 1);
        atomicAdd(&g_count[d4.w], 1);
    }
}

// ---------------- K1: node precompute (register-tiled GEMM) ----------------
__global__ __launch_bounds__(256, 2) void k_node(const float* __restrict__ x,
                                                 const float* __restrict__ W1,
                                                 const float* __restrict__ W2,
                                                 const float* __restrict__ attn) {
    __shared__ float xS[TM][65];
    __shared__ float sW[DIN][128];        // [k][d]; d<64: W1a, d>=64: W2
    __shared__ float sAttnR[DIN];

    const int tid = threadIdx.x;
    const int n0  = blockIdx.x * TM;

    for (int idx = tid; idx < DIN * 128; idx += 256) {
        int k = idx >> 7, d = idx & 127;
        sW[k][d] = (d < 64) ? W1[d * (DIN + DEDGE) + k]
                            : W2[(d - 64) * DIN + k];
    }
    if (tid < DIN) sAttnR[tid] = attn[DOUT + tid];

    for (int idx = tid; idx < TM * DIN; idx += 256) {
        int nl = idx >> 6, k = idx & 63;
        int n = n0 + nl;
        if (n >= NN) n = NN - 1;
        xS[nl][k] = x[n * DIN + k];
    }
    __syncthreads();

    const int ty = tid >> 4, tx = tid & 15;
    const int nbase = ty * 8;

    ull acc[8][4];
    #pragma unroll
    for (int j = 0; j < 8; j++)
        #pragma unroll
        for (int p = 0; p < 4; p++) acc[j][p] = 0ULL;

    #pragma unroll 4
    for (int k = 0; k < DIN; k++) {
        ulonglong2 wA = *reinterpret_cast<const ulonglong2*>(&sW[k][tx * 8]);
        ulonglong2 wB = *reinterpret_cast<const ulonglong2*>(&sW[k][tx * 8 + 4]);
        #pragma unroll
        for (int j = 0; j < 8; j++) {
            float xv = xS[nbase + j][k];
            ull xp = packf2(xv, xv);
            ffma2(acc[j][0], wA.x, xp);
            ffma2(acc[j][1], wA.y, xp);
            ffma2(acc[j][2], wB.x, xp);
            ffma2(acc[j][3], wB.y, xp);
        }
    }

    if (tid < TM) {
        int n = n0 + tid;
        if (n < NN) {
            float rd = 0.0f;
            #pragma unroll 8
            for (int k = 0; k < DIN; k++)
                rd += leaky(xS[tid][k]) * sAttnR[k];
            g_rdot[n] = rd;
        }
    }

    #pragma unroll
    for (int j = 0; j < 8; j++) {
        int n = n0 + nbase + j;
        if (n >= NN) continue;
        float* dstp = (tx < 8) ? &g_sf[n * DOUT + tx * 8]
                               : &g_xt[n * DOUT + (tx - 8) * 8];
        ulonglong2 v0; v0.x = acc[j][0]; v0.y = acc[j][1];
        ulonglong2 v1; v1.x = acc[j][2]; v1.y = acc[j][3];
        *reinterpret_cast<ulonglong2*>(dstp)     = v0;
        *reinterpret_cast<ulonglong2*>(dstp + 4) = v1;
    }
}

// ---------------- scan counts -> rowptr ----------------
__global__ __launch_bounds__(SCAN_T) void k_scan1() {
    __shared__ int sh[SCAN_T];
    int i = blockIdx.x * SCAN_T + threadIdx.x;
    int v = (i < NN) ? g_count[i] : 0;
    sh[threadIdx.x] = v;
    __syncthreads();
    #pragma unroll
    for (int off = 1; off < SCAN_T; off <<= 1) {
        int t = (threadIdx.x >= off) ? sh[threadIdx.x - off] : 0;
        __syncthreads();
        sh[threadIdx.x] += t;
        __syncthreads();
    }
    if (i < NN) g_rowptr[i] = sh[threadIdx.x] - v;   // exclusive
    if (threadIdx.x == SCAN_T - 1) g_bsum[blockIdx.x] = sh[SCAN_T - 1];
}

// fused scan of block sums (redundant per block, trivial) + rowptr finalize
__global__ __launch_bounds__(256) void k_scan23() {
    __shared__ int sh[256];
    __shared__ int exs[256];
    int t = threadIdx.x;
    int v = (t < SCAN_BLOCKS) ? g_bsum[t] : 0;
    sh[t] = v;
    __syncthreads();
    #pragma unroll
    for (int off = 1; off < 256; off <<= 1) {
        int tv = (t >= off) ? sh[t - off] : 0;
        __syncthreads();
        sh[t] += tv;
        __syncthreads();
    }
    exs[t] = sh[t] - v;                   // exclusive
    __syncthreads();

    int i = blockIdx.x * 256 + t;
    if (i < NN) {
        int r = g_rowptr[i] + exs[i >> 9];
        g_rowptr[i] = r;
        g_wptr[i]   = r;
    }
    if (i == 0) g_rowptr[NN] = EE;
}

// ---------------- K2: per-edge logits, transpose-reduced, per-lane scatter ----
// R6 structure; latency fix: accumulate from ZERO in two chains (sf gather
// latency overlaps the FFMA2 work, added at the end), unroll 4 for MLP.
__global__ __launch_bounds__(256) void k_logits(const float* __restrict__ edge_attr,
                                                const int* __restrict__ src,
                                                const int* __restrict__ dst,
                                                const float* __restrict__ W1,
                                                const float* __restrict__ attn) {
    __shared__ float2 sW[DEDGE * 32];    // [k][L] = (W1b[2L][k], W1b[2L+1][k])
    __shared__ float  sP[8][32][33];     // [warp][edge][lane], padded

    for (int idx = threadIdx.x; idx < DEDGE * 32; idx += blockDim.x) {
        int k = idx >> 5, L = idx & 31;
        sW[idx] = make_float2(W1[(2 * L) * (DIN + DEDGE) + DIN + k],
                              W1[(2 * L + 1) * (DIN + DEDGE) + DIN + k]);
    }
    __syncthreads();

    const int L = threadIdx.x & 31;
    const int w = threadIdx.x >> 5;

    ull wp[DEDGE];
    #pragma unroll
    for (int k = 0; k < DEDGE; k++) {
        float2 t = sW[k * 32 + L];
        wp[k] = packf2(t.x, t.y);
    }
    const float aL = __ldg(&attn[2 * L]);
    const float aH = __ldg(&attn[2 * L + 1]);

    const int gwarp = blockIdx.x * 8 + w;        // 256 edges/block
    const int base  = gwarp * 32;

    const int s_own = src[base + L];     // coalesced
    const int d_own = dst[base + L];     // coalesced
    const float4* ea4 = (const float4*)edge_attr;

    // Phase A: partials. Gather issued first; FFMA2 chains start at zero so
    // the 234-cycle L2 latency hides under the math; sf added at the end.
    #pragma unroll 4
    for (int i = 0; i < 32; i++) {
        const int e = base + i;
        const int s = __shfl_sync(0xFFFFFFFFu, s_own, i);

        float2 sf = *reinterpret_cast<const float2*>(&g_sf[s * DOUT + 2 * L]);

        ull f0 = 0ULL, f1 = 0ULL;
        float4 ev0 = __ldg(&ea4[e * 4 + 0]);
        ffma2(f0, wp[0], packf2(ev0.x, ev0.x));
        ffma2(f1, wp[1], packf2(ev0.y, ev0.y));
        ffma2(f0, wp[2], packf2(ev0.z, ev0.z));
        ffma2(f1, wp[3], packf2(ev0.w, ev0.w));
        float4 ev1 = __ldg(&ea4[e * 4 + 1]);
        ffma2(f0, wp[4], packf2(ev1.x, ev1.x));
        ffma2(f1, wp[5], packf2(ev1.y, ev1.y));
        ffma2(f0, wp[6], packf2(ev1.z, ev1.z));
        ffma2(f1, wp[7], packf2(ev1.w, ev1.w));
        float4 ev2 = __ldg(&ea4[e * 4 + 2]);
        ffma2(f0, wp[8],  packf2(ev2.x, ev2.x));
        ffma2(f1, wp[9],  packf2(ev2.y, ev2.y));
        ffma2(f0, wp[10], packf2(ev2.z, ev2.z));
        ffma2(f1, wp[11], packf2(ev2.w, ev2.w));
        float4 ev3 = __ldg(&ea4[e * 4 + 3]);
        ffma2(f0, wp[12], packf2(ev3.x, ev3.x));
        ffma2(f1, wp[13], packf2(ev3.y, ev3.y));
        ffma2(f0, wp[14], packf2(ev3.z, ev3.z));
        ffma2(f1, wp[15], packf2(ev3.w, ev3.w));

        float a0, a1, b0, b1;
        unpackf2(f0, a0, a1);
        unpackf2(f1, b0, b1);
        float flo = sf.x + a0 + b0;
        float fhi = sf.y + a1 + b1;
        sP[w][i][L] = leaky(flo) * aL + leaky(fhi) * aH;
    }
    __syncwarp();

    // Phase B: lane L reduces its own edge (row L), conflict-free via pad 33
    float s0 = 0.f, s1 = 0.f, s2 = 0.f, s3 = 0.f;
    #pragma unroll
    for (int j = 0; j < 32; j += 4) {
        s0 += sP[w][L][j];
        s1 += sP[w][L][j + 1];
        s2 += sP[w][L][j + 2];
        s3 += sP[w][L][j + 3];
    }
    float logit = (s0 + s1) + (s2 + s3) + g_rdot[d_own];

    int pos = atomicAdd(&g_wptr[d_own], 1);               // spread-address
    g_ls[pos] = make_float2(logit, __int_as_float(s_own));
}

// ---------------- K5: warp-per-dst softmax + aggregation ----------------
__global__ __launch_bounds__(256) void k_aggregate(const float* __restrict__ bias,
                                                   float* __restrict__ out) {
    __shared__ float2 sA[8][32];          // [warp][idx] = {alpha, src-bits}

    const int lane = threadIdx.x & 31;
    const int w    = threadIdx.x >> 5;
    const int gw   = (blockIdx.x * blockDim.x + threadIdx.x) >> 5;
    if (gw >= NN) return;
    const int n = gw;

    int beg = g_rowptr[n];
    int end = g_rowptr[n + 1];
    int cnt = end - beg;

    float b0 = bias[2 * lane];
    float b1 = bias[2 * lane + 1];

    if (cnt == 0) {
        out[n * DOUT + 2 * lane]     = b0;
        out[n * DOUT + 2 * lane + 1] = b1;
        return;
    }

    float2 v = make_float2(-INFINITY, 0.0f);
    if (lane < cnt) v = g_ls[beg + lane];

    float lm = v.x;
    for (int j = beg + 32 + lane; j < end; j += 32)
        lm = fmaxf(lm, g_ls[j].x);
    float m = warp_max(lm);

    float le = (lane < cnt) ? __expf(v.x - m) : 0.0f;
    for (int j = beg + 32 + lane; j < end; j += 32)
        le += __expf(g_ls[j].x - m);
    float inv = 1.0f / warp_sum(le);

    sA[w][lane] = make_float2((lane < cnt) ? __expf(v.x - m) * inv : 0.0f, v.y);
    __syncwarp();

    float acc0 = 0.0f, acc1 = 0.0f;
    int lim = cnt < 32 ? cnt : 32;
    #pragma unroll 4
    for (int idx = 0; idx < lim; idx++) {
        float2 t = sA[w][idx];            // broadcast LDS.64
        int   s = __float_as_int(t.y);
        float a = t.x;
        float2 xv = *reinterpret_cast<const float2*>(&g_xt[s * DOUT + 2 * lane]);
        acc0 = fmaf(a, xv.x, acc0);
        acc1 = fmaf(a, xv.y, acc1);
    }
    for (int j = beg + 32; j < end; j++) {
        float2 lsv = g_ls[j];
        int   s = __float_as_int(lsv.y);
        float a = __expf(lsv.x - m) * inv;
        float2 xv = *reinterpret_cast<const float2*>(&g_xt[s * DOUT + 2 * lane]);
        acc0 = fmaf(a, xv.x, acc0);
        acc1 = fmaf(a, xv.y, acc1);
    }
    out[n * DOUT + 2 * lane]     = acc0 + b0;
    out[n * DOUT + 2 * lane + 1] = acc1 + b1;
}

// ---------------- launch ----------------
extern "C" void kernel_launch(void* const* d_in, const int* in_sizes, int n_in,
                              void* d_out, int out_size) {
    const float* x         = (const float*)d_in[0];
    const float* edge_attr = (const float*)d_in[1];
    const int*   src       = (const int*)d_in[2];
    const int*   dst       = (const int*)d_in[3];
    const float* W1        = (const float*)d_in[4];
    const float* W2        = (const float*)d_in[5];
    const float* attn      = (const float*)d_in[6];
    const float* bias      = (const float*)d_in[7];
    float* out             = (float*)d_out;

    void* count_ptr = nullptr;
    cudaGetSymbolAddress(&count_ptr, g_count);
    cudaMemsetAsync(count_ptr, 0, NN * sizeof(int));

    k_hist<<<(EE / 4 + 255) / 256, 256>>>(dst);
    k_node<<<NODE_BLOCKS, 256>>>(x, W1, W2, attn);
    k_scan1<<<SCAN_BLOCKS, SCAN_T>>>();
    k_scan23<<<(NN + 255) / 256, 256>>>();
    k_logits<<<EE / 256, 256>>>(edge_attr, src, dst, W1, attn);
    k_aggregate<<<(NN * 32 + 255) / 256, 256>>>(bias, out);
}

// round 15
// speedup vs baseline: 1.2442x; 1.2442x over previous
#include <cuda_runtime.h>
#include <math.h>

#define NN 100000
#define EE 1280000
#define DIN 64
#define DOUT 64
#define DEDGE 16
#define NEG 0.01f

#define SCAN_T 512
#define SCAN_BLOCKS ((NN + SCAN_T - 1) / SCAN_T)   // 196

#define TM 128                                     // nodes per k_node block
#define NODE_BLOCKS ((NN + TM - 1) / TM)           // 782

typedef unsigned long long ull;

// ---------------- device scratch (static, no allocation) ----------------
__device__ float  g_xt[NN * DOUT];      // x @ W2^T, natural [n][d]
__device__ float  g_sf[NN * DOUT];      // x @ W1a^T, natural [n][d]
__device__ float  g_rdot[NN];
__device__ float2 g_ls[EE];             // CSR-ordered {logit, src-as-bits}
__device__ int    g_count[NN];
__device__ int    g_rowptr[NN + 1];
__device__ int    g_wptr[NN];
__device__ int    g_bsum[SCAN_BLOCKS];

__device__ __forceinline__ float leaky(float v) {
    return fmaxf(v, NEG * v);
}
__device__ __forceinline__ float warp_sum(float v) {
    #pragma unroll
    for (int o = 16; o > 0; o >>= 1) v += __shfl_xor_sync(0xFFFFFFFFu, v, o);
    return v;
}
__device__ __forceinline__ float warp_max(float v) {
    #pragma unroll
    for (int o = 16; o > 0; o >>= 1) v = fmaxf(v, __shfl_xor_sync(0xFFFFFFFFu, v, o));
    return v;
}

// packed f32x2 helpers
__device__ __forceinline__ ull packf2(float lo, float hi) {
    ull r;
    asm("mov.b64 %0, {%1, %2};" : "=l"(r) : "f"(lo), "f"(hi));
    return r;
}
__device__ __forceinline__ void unpackf2(ull v, float& lo, float& hi) {
    asm("mov.b64 {%0, %1}, %2;" : "=f"(lo), "=f"(hi) : "l"(v));
}
__device__ __forceinline__ void ffma2(ull& acc, ull a, ull b) {
    asm("fma.rn.f32x2 %0, %1, %2, %0;" : "+l"(acc) : "l"(a), "l"(b));
}

// ---------------- Kh: dst histogram (4 edges/thread) ----------------
__global__ __launch_bounds__(256) void k_hist(const int* __restrict__ dst) {
    int t = blockIdx.x * blockDim.x + threadIdx.x;
    if (t * 4 < EE) {
        int4 d4 = ((const int4*)dst)[t];
        atomicAdd(&g_count[d4.x], 1);
        atomicAdd(&g_count[d4.y], 1);
        atomicAdd(&g_count[d4.z], 1);
        atomicAdd(&g_count[d4.w], 1);
    }
}

// ---------------- K1: node precompute (register-tiled GEMM) ----------------
__global__ __launch_bounds__(256, 2) void k_node(const float* __restrict__ x,
                                                 const float* __restrict__ W1,
                                                 const float* __restrict__ W2,
                                                 const float* __restrict__ attn) {
    __shared__ float xS[TM][65];
    __shared__ float sW[DIN][128];        // [k][d]; d<64: W1a, d>=64: W2
    __shared__ float sAttnR[DIN];

    const int tid = threadIdx.x;
    const int n0  = blockIdx.x * TM;

    for (int idx = tid; idx < DIN * 128; idx += 256) {
        int k = idx >> 7, d = idx & 127;
        sW[k][d] = (d < 64) ? W1[d * (DIN + DEDGE) + k]
                            : W2[(d - 64) * DIN + k];
    }
    if (tid < DIN) sAttnR[tid] = attn[DOUT + tid];

    for (int idx = tid; idx < TM * DIN; idx += 256) {
        int nl = idx >> 6, k = idx & 63;
        int n = n0 + nl;
        if (n >= NN) n = NN - 1;
        xS[nl][k] = x[n * DIN + k];
    }
    __syncthreads();

    const int ty = tid >> 4, tx = tid & 15;
    const int nbase = ty * 8;

    ull acc[8][4];
    #pragma unroll
    for (int j = 0; j < 8; j++)
        #pragma unroll
        for (int p = 0; p < 4; p++) acc[j][p] = 0ULL;

    #pragma unroll 4
    for (int k = 0; k < DIN; k++) {
        ulonglong2 wA = *reinterpret_cast<const ulonglong2*>(&sW[k][tx * 8]);
        ulonglong2 wB = *reinterpret_cast<const ulonglong2*>(&sW[k][tx * 8 + 4]);
        #pragma unroll
        for (int j = 0; j < 8; j++) {
            float xv = xS[nbase + j][k];
            ull xp = packf2(xv, xv);
            ffma2(acc[j][0], wA.x, xp);
            ffma2(acc[j][1], wA.y, xp);
            ffma2(acc[j][2], wB.x, xp);
            ffma2(acc[j][3], wB.y, xp);
        }
    }

    if (tid < TM) {
        int n = n0 + tid;
        if (n < NN) {
            float rd = 0.0f;
            #pragma unroll 8
            for (int k = 0; k < DIN; k++)
                rd += leaky(xS[tid][k]) * sAttnR[k];
            g_rdot[n] = rd;
        }
    }

    #pragma unroll
    for (int j = 0; j < 8; j++) {
        int n = n0 + nbase + j;
        if (n >= NN) continue;
        float* dstp = (tx < 8) ? &g_sf[n * DOUT + tx * 8]
                               : &g_xt[n * DOUT + (tx - 8) * 8];
        ulonglong2 v0; v0.x = acc[j][0]; v0.y = acc[j][1];
        ulonglong2 v1; v1.x = acc[j][2]; v1.y = acc[j][3];
        *reinterpret_cast<ulonglong2*>(dstp)     = v0;
        *reinterpret_cast<ulonglong2*>(dstp + 4) = v1;
    }
}

// ---------------- scan counts -> rowptr ----------------
__global__ __launch_bounds__(SCAN_T) void k_scan1() {
    __shared__ int sh[SCAN_T];
    int i = blockIdx.x * SCAN_T + threadIdx.x;
    int v = (i < NN) ? g_count[i] : 0;
    sh[threadIdx.x] = v;
    __syncthreads();
    #pragma unroll
    for (int off = 1; off < SCAN_T; off <<= 1) {
        int t = (threadIdx.x >= off) ? sh[threadIdx.x - off] : 0;
        __syncthreads();
        sh[threadIdx.x] += t;
        __syncthreads();
    }
    if (i < NN) g_rowptr[i] = sh[threadIdx.x] - v;   // exclusive
    if (threadIdx.x == SCAN_T - 1) g_bsum[blockIdx.x] = sh[SCAN_T - 1];
}

// fused scan of block sums (redundant per block, trivial) + rowptr finalize
__global__ __launch_bounds__(256) void k_scan23() {
    __shared__ int sh[256];
    __shared__ int exs[256];
    int t = threadIdx.x;
    int v = (t < SCAN_BLOCKS) ? g_bsum[t] : 0;
    sh[t] = v;
    __syncthreads();
    #pragma unroll
    for (int off = 1; off < 256; off <<= 1) {
        int tv = (t >= off) ? sh[t - off] : 0;
        __syncthreads();
        sh[t] += tv;
        __syncthreads();
    }
    exs[t] = sh[t] - v;                   // exclusive
    __syncthreads();

    int i = blockIdx.x * 256 + t;
    if (i < NN) {
        int r = g_rowptr[i] + exs[i >> 9];
        g_rowptr[i] = r;
        g_wptr[i]   = r;
    }
    if (i == 0) g_rowptr[NN] = EE;
}

// ---------------- K2: per-edge logits, transpose-reduced, per-lane scatter ----
// R6/R13-proven form, untouched.
__global__ __launch_bounds__(256) void k_logits(const float* __restrict__ edge_attr,
                                                const int* __restrict__ src,
                                                const int* __restrict__ dst,
                                                const float* __restrict__ W1,
                                                const float* __restrict__ attn) {
    __shared__ float2 sW[DEDGE * 32];    // [k][L] = (W1b[2L][k], W1b[2L+1][k])
    __shared__ float  sP[8][32][33];     // [warp][edge][lane], padded

    for (int idx = threadIdx.x; idx < DEDGE * 32; idx += blockDim.x) {
        int k = idx >> 5, L = idx & 31;
        sW[idx] = make_float2(W1[(2 * L) * (DIN + DEDGE) + DIN + k],
                              W1[(2 * L + 1) * (DIN + DEDGE) + DIN + k]);
    }
    __syncthreads();

    const int L = threadIdx.x & 31;
    const int w = threadIdx.x >> 5;

    ull wp[DEDGE];
    #pragma unroll
    for (int k = 0; k < DEDGE; k++) {
        float2 t = sW[k * 32 + L];
        wp[k] = packf2(t.x, t.y);
    }
    const float aL = __ldg(&attn[2 * L]);
    const float aH = __ldg(&attn[2 * L + 1]);

    const int gwarp = blockIdx.x * 8 + w;        // 256 edges/block
    const int base  = gwarp * 32;

    const int s_own = src[base + L];     // coalesced
    const int d_own = dst[base + L];     // coalesced
    const float4* ea4 = (const float4*)edge_attr;

    // Phase A: partials
    #pragma unroll 2
    for (int i = 0; i < 32; i++) {
        const int e = base + i;
        const int s = __shfl_sync(0xFFFFFFFFu, s_own, i);

        float2 sf = *reinterpret_cast<const float2*>(&g_sf[s * DOUT + 2 * L]);
        ull f = packf2(sf.x, sf.y);

        #pragma unroll
        for (int g = 0; g < 4; g++) {
            float4 ev = __ldg(&ea4[e * 4 + g]);           // lane-uniform broadcast
            ffma2(f, wp[4 * g + 0], packf2(ev.x, ev.x));
            ffma2(f, wp[4 * g + 1], packf2(ev.y, ev.y));
            ffma2(f, wp[4 * g + 2], packf2(ev.z, ev.z));
            ffma2(f, wp[4 * g + 3], packf2(ev.w, ev.w));
        }

        float flo, fhi;
        unpackf2(f, flo, fhi);
        sP[w][i][L] = leaky(flo) * aL + leaky(fhi) * aH;
    }
    __syncwarp();

    // Phase B: lane L reduces its own edge (row L), conflict-free via pad 33
    float s0 = 0.f, s1 = 0.f, s2 = 0.f, s3 = 0.f;
    #pragma unroll
    for (int j = 0; j < 32; j += 4) {
        s0 += sP[w][L][j];
        s1 += sP[w][L][j + 1];
        s2 += sP[w][L][j + 2];
        s3 += sP[w][L][j + 3];
    }
    float logit = (s0 + s1) + (s2 + s3) + g_rdot[d_own];

    int pos = atomicAdd(&g_wptr[d_own], 1);               // spread-address
    g_ls[pos] = make_float2(logit, __int_as_float(s_own));
}

// ---------------- K5: warp-per-dst softmax + aggregation ----------------
__global__ __launch_bounds__(256) void k_aggregate(const float* __restrict__ bias,
                                                   float* __restrict__ out) {
    __shared__ float2 sA[8][32];          // [warp][idx] = {alpha, src-bits}

    const int lane = threadIdx.x & 31;
    const int w    = threadIdx.x >> 5;
    const int gw   = (blockIdx.x * blockDim.x + threadIdx.x) >> 5;
    if (gw >= NN) return;
    const int n = gw;

    int beg = g_rowptr[n];
    int end = g_rowptr[n + 1];
    int cnt = end - beg;

    float b0 = bias[2 * lane];
    float b1 = bias[2 * lane + 1];

    if (cnt == 0) {
        out[n * DOUT + 2 * lane]     = b0;
        out[n * DOUT + 2 * lane + 1] = b1;
        return;
    }

    float2 v = make_float2(-INFINITY, 0.0f);
    if (lane < cnt) v = g_ls[beg + lane];

    float lm = v.x;
    for (int j = beg + 32 + lane; j < end; j += 32)
        lm = fmaxf(lm, g_ls[j].x);
    float m = warp_max(lm);

    float le = (lane < cnt) ? __expf(v.x - m) : 0.0f;
    for (int j = beg + 32 + lane; j < end; j += 32)
        le += __expf(g_ls[j].x - m);
    float inv = 1.0f / warp_sum(le);

    sA[w][lane] = make_float2((lane < cnt) ? __expf(v.x - m) * inv : 0.0f, v.y);
    __syncwarp();

    float acc0 = 0.0f, acc1 = 0.0f;
    int lim = cnt < 32 ? cnt : 32;
    #pragma unroll 4
    for (int idx = 0; idx < lim; idx++) {
        float2 t = sA[w][idx];            // broadcast LDS.64
        int   s = __float_as_int(t.y);
        float a = t.x;
        float2 xv = *reinterpret_cast<const float2*>(&g_xt[s * DOUT + 2 * lane]);
        acc0 = fmaf(a, xv.x, acc0);
        acc1 = fmaf(a, xv.y, acc1);
    }
    for (int j = beg + 32; j < end; j++) {
        float2 lsv = g_ls[j];
        int   s = __float_as_int(lsv.y);
        float a = __expf(lsv.x - m) * inv;
        float2 xv = *reinterpret_cast<const float2*>(&g_xt[s * DOUT + 2 * lane]);
        acc0 = fmaf(a, xv.x, acc0);
        acc1 = fmaf(a, xv.y, acc1);
    }
    out[n * DOUT + 2 * lane]     = acc0 + b0;
    out[n * DOUT + 2 * lane + 1] = acc1 + b1;
}

// ---------------- launch: fork-join dual-stream (graph-capturable) ----------
extern "C" void kernel_launch(void* const* d_in, const int* in_sizes, int n_in,
                              void* d_out, int out_size) {
    const float* x         = (const float*)d_in[0];
    const float* edge_attr = (const float*)d_in[1];
    const int*   src       = (const int*)d_in[2];
    const int*   dst       = (const int*)d_in[3];
    const float* W1        = (const float*)d_in[4];
    const float* W2        = (const float*)d_in[5];
    const float* attn      = (const float*)d_in[6];
    const float* bias      = (const float*)d_in[7];
    float* out             = (float*)d_out;

    // One-time host-side resources (created on the first, non-captured call;
    // no device memory allocation involved).
    static cudaStream_t side = nullptr;
    static cudaEvent_t  evFork = nullptr, evJoin = nullptr;
    if (side == nullptr) {
        cudaStreamCreateWithFlags(&side, cudaStreamNonBlocking);
        cudaEventCreateWithFlags(&evFork, cudaEventDisableTiming);
        cudaEventCreateWithFlags(&evJoin, cudaEventDisableTiming);
    }

    void* count_ptr = nullptr;
    cudaGetSymbolAddress(&count_ptr, g_count);

    // fork: side stream runs the hist/scan chain concurrently with k_node
    cudaEventRecord(evFork, 0);
    cudaStreamWaitEvent(side, evFork, 0);

    cudaMemsetAsync(count_ptr, 0, NN * sizeof(int), side);
    k_hist<<<(EE / 4 + 255) / 256, 256, 0, side>>>(dst);
    k_scan1<<<SCAN_BLOCKS, SCAN_T, 0, side>>>();
    k_scan23<<<(NN + 255) / 256, 256, 0, side>>>();
    cudaEventRecord(evJoin, side);

    k_node<<<NODE_BLOCKS, 256>>>(x, W1, W2, attn);

    // join: logits needs both k_node outputs and wptr
    cudaStreamWaitEvent(0, evJoin, 0);
    k_logits<<<EE / 256, 256>>>(edge_attr, src, dst, W1, attn);
    k_aggregate<<<(NN * 32 + 255) / 256, 256>>>(bias, out);
}

// round 16
// speedup vs baseline: 1.2635x; 1.0155x over previous
#include <cuda_runtime.h>
#include <math.h>

#define NN 100000
#define EE 1280000
#define DIN 64
#define DOUT 64
#define DEDGE 16
#define NEG 0.01f

#define SCAN_T 512
#define SCAN_BLOCKS ((NN + SCAN_T - 1) / SCAN_T)   // 196

#define TM 128                                     // nodes per k_node block
#define NODE_BLOCKS ((NN + TM - 1) / TM)           // 782
#define XPAD 132                                   // xT row pad: 16B-aligned rows, 4-way fill conflict

typedef unsigned long long ull;

// ---------------- device scratch (static, no allocation) ----------------
__device__ float  g_xt[NN * DOUT];      // x @ W2^T, natural [n][d]
__device__ float  g_sf[NN * DOUT];      // x @ W1a^T, natural [n][d]
__device__ float  g_rdot[NN];
__device__ float2 g_ls[EE];             // CSR-ordered {logit, src-as-bits}
__device__ int    g_count[NN];
__device__ int    g_rowptr[NN + 1];
__device__ int    g_wptr[NN];
__device__ int    g_bsum[SCAN_BLOCKS];

__device__ __forceinline__ float leaky(float v) {
    return fmaxf(v, NEG * v);
}
__device__ __forceinline__ float warp_sum(float v) {
    #pragma unroll
    for (int o = 16; o > 0; o >>= 1) v += __shfl_xor_sync(0xFFFFFFFFu, v, o);
    return v;
}
__device__ __forceinline__ float warp_max(float v) {
    #pragma unroll
    for (int o = 16; o > 0; o >>= 1) v = fmaxf(v, __shfl_xor_sync(0xFFFFFFFFu, v, o));
    return v;
}

// packed f32x2 helpers
__device__ __forceinline__ ull packf2(float lo, float hi) {
    ull r;
    asm("mov.b64 %0, {%1, %2};" : "=l"(r) : "f"(lo), "f"(hi));
    return r;
}
__device__ __forceinline__ void unpackf2(ull v, float& lo, float& hi) {
    asm("mov.b64 {%0, %1}, %2;" : "=f"(lo), "=f"(hi) : "l"(v));
}
__device__ __forceinline__ void ffma2(ull& acc, ull a, ull b) {
    asm("fma.rn.f32x2 %0, %1, %2, %0;" : "+l"(acc) : "l"(a), "l"(b));
}

// ---------------- Kh: dst histogram (4 edges/thread) ----------------
__global__ __launch_bounds__(256) void k_hist(const int* __restrict__ dst) {
    int t = blockIdx.x * blockDim.x + threadIdx.x;
    if (t * 4 < EE) {
        int4 d4 = ((const int4*)dst)[t];
        atomicAdd(&g_count[d4.x], 1);
        atomicAdd(&g_count[d4.y], 1);
        atomicAdd(&g_count[d4.z], 1);
        atomicAdd(&g_count[d4.w], 1);
    }
}

// ---------------- K1: node precompute (node-paired register GEMM) ----------
// x transposed in shared: xT[k][node]. Lane's x operand = 2 broadcast LDS.128
// yielding 4 ready f32x2 node-pairs per k (no packing). acc[p][d] accumulates
// output dims 8tx+d for node pair (nbase+2p, nbase+2p+1).
__global__ __launch_bounds__(256, 2) void k_node(const float* __restrict__ x,
                                                 const float* __restrict__ W1,
                                                 const float* __restrict__ W2,
                                                 const float* __restrict__ attn) {
    __shared__ float xT[DIN][XPAD];       // [k][node]
    __shared__ float sW[DIN][128];        // [k][d]; d<64: W1a, d>=64: W2
    __shared__ float sAttnR[DIN];

    const int tid = threadIdx.x;
    const int n0  = blockIdx.x * TM;

    for (int idx = tid; idx < DIN * 128; idx += 256) {
        int k = idx >> 7, d = idx & 127;
        sW[k][d] = (d < 64) ? W1[d * (DIN + DEDGE) + k]
                            : W2[(d - 64) * DIN + k];
    }
    if (tid < DIN) sAttnR[tid] = attn[DOUT + tid];

    // transposed fill: coalesced gmem read, 4-way STS conflict (one-time)
    for (int idx = tid; idx < TM * DIN; idx += 256) {
        int nl = idx >> 6, k = idx & 63;
        int n = n0 + nl;
        if (n >= NN) n = NN - 1;
        xT[k][nl] = x[n * DIN + k];
    }
    __syncthreads();

    const int ty = tid >> 4, tx = tid & 15;
    const int nbase = ty * 8;

    ull acc[4][8];                        // [node-pair][dim]
    #pragma unroll
    for (int p = 0; p < 4; p++)
        #pragma unroll
        for (int d = 0; d < 8; d++) acc[p][d] = 0ULL;

    #pragma unroll 4
    for (int k = 0; k < DIN; k++) {
        // 8 node values = 4 f32x2 pairs, direct from LDS.128 (broadcast, 1 wf)
        ulonglong2 xp0 = *reinterpret_cast<const ulonglong2*>(&xT[k][nbase]);
        ulonglong2 xp1 = *reinterpret_cast<const ulonglong2*>(&xT[k][nbase + 4]);
        // 8 weights for this thread's dims
        float4 w0 = *reinterpret_cast<const float4*>(&sW[k][tx * 8]);
        float4 w1 = *reinterpret_cast<const float4*>(&sW[k][tx * 8 + 4]);
        ull wd0 = packf2(w0.x, w0.x), wd1 = packf2(w0.y, w0.y);
        ull wd2 = packf2(w0.z, w0.z), wd3 = packf2(w0.w, w0.w);
        ull wd4 = packf2(w1.x, w1.x), wd5 = packf2(w1.y, w1.y);
        ull wd6 = packf2(w1.z, w1.z), wd7 = packf2(w1.w, w1.w);
        ull xp[4] = {xp0.x, xp0.y, xp1.x, xp1.y};
        #pragma unroll
        for (int p = 0; p < 4; p++) {
            ffma2(acc[p][0], xp[p], wd0);
            ffma2(acc[p][1], xp[p], wd1);
            ffma2(acc[p][2], xp[p], wd2);
            ffma2(acc[p][3], xp[p], wd3);
            ffma2(acc[p][4], xp[p], wd4);
            ffma2(acc[p][5], xp[p], wd5);
            ffma2(acc[p][6], xp[p], wd6);
            ffma2(acc[p][7], xp[p], wd7);
        }
    }

    // rdot: thread tid handles node n0+tid; xT[k][tid] is conflict-free
    if (tid < TM) {
        int n = n0 + tid;
        if (n < NN) {
            float rd = 0.0f;
            #pragma unroll 8
            for (int k = 0; k < DIN; k++)
                rd += leaky(xT[k][tid]) * sAttnR[k];
            g_rdot[n] = rd;
        }
    }

    // store: extract lo/hi halves per node, 2 STG.128 per node
    #pragma unroll
    for (int p = 0; p < 4; p++) {
        float lo[8], hi[8];
        #pragma unroll
        for (int d = 0; d < 8; d++) unpackf2(acc[p][d], lo[d], hi[d]);

        int nA = n0 + nbase + 2 * p;
        int nB = nA + 1;
        if (nA < NN) {
            float* dstp = (tx < 8) ? &g_sf[nA * DOUT + tx * 8]
                                   : &g_xt[nA * DOUT + (tx - 8) * 8];
            *reinterpret_cast<float4*>(dstp)     = make_float4(lo[0], lo[1], lo[2], lo[3]);
            *reinterpret_cast<float4*>(dstp + 4) = make_float4(lo[4], lo[5], lo[6], lo[7]);
        }
        if (nB < NN) {
            float* dstp = (tx < 8) ? &g_sf[nB * DOUT + tx * 8]
                                   : &g_xt[nB * DOUT + (tx - 8) * 8];
            *reinterpret_cast<float4*>(dstp)     = make_float4(hi[0], hi[1], hi[2], hi[3]);
            *reinterpret_cast<float4*>(dstp + 4) = make_float4(hi[4], hi[5], hi[6], hi[7]);
        }
    }
}

// ---------------- scan counts -> rowptr ----------------
__global__ __launch_bounds__(SCAN_T) void k_scan1() {
    __shared__ int sh[SCAN_T];
    int i = blockIdx.x * SCAN_T + threadIdx.x;
    int v = (i < NN) ? g_count[i] : 0;
    sh[threadIdx.x] = v;
    __syncthreads();
    #pragma unroll
    for (int off = 1; off < SCAN_T; off <<= 1) {
        int t = (threadIdx.x >= off) ? sh[threadIdx.x - off] : 0;
        __syncthreads();
        sh[threadIdx.x] += t;
        __syncthreads();
    }
    if (i < NN) g_rowptr[i] = sh[threadIdx.x] - v;   // exclusive
    if (threadIdx.x == SCAN_T - 1) g_bsum[blockIdx.x] = sh[SCAN_T - 1];
}

// fused scan of block sums (redundant per block, trivial) + rowptr finalize
__global__ __launch_bounds__(256) void k_scan23() {
    __shared__ int sh[256];
    __shared__ int exs[256];
    int t = threadIdx.x;
    int v = (t < SCAN_BLOCKS) ? g_bsum[t] : 0;
    sh[t] = v;
    __syncthreads();
    #pragma unroll
    for (int off = 1; off < 256; off <<= 1) {
        int tv = (t >= off) ? sh[t - off] : 0;
        __syncthreads();
        sh[t] += tv;
        __syncthreads();
    }
    exs[t] = sh[t] - v;                   // exclusive
    __syncthreads();

    int i = blockIdx.x * 256 + t;
    if (i < NN) {
        int r = g_rowptr[i] + exs[i >> 9];
        g_rowptr[i] = r;
        g_wptr[i]   = r;
    }
    if (i == 0) g_rowptr[NN] = EE;
}

// ---------------- K2: per-edge logits, transpose-reduced, per-lane scatter ----
// R6/R13-proven form, untouched.
__global__ __launch_bounds__(256) void k_logits(const float* __restrict__ edge_attr,
                                                const int* __restrict__ src,
                                                const int* __restrict__ dst,
                                                const float* __restrict__ W1,
                                                const float* __restrict__ attn) {
    __shared__ float2 sW[DEDGE * 32];    // [k][L] = (W1b[2L][k], W1b[2L+1][k])
    __shared__ float  sP[8][32][33];     // [warp][edge][lane], padded

    for (int idx = threadIdx.x; idx < DEDGE * 32; idx += blockDim.x) {
        int k = idx >> 5, L = idx & 31;
        sW[idx] = make_float2(W1[(2 * L) * (DIN + DEDGE) + DIN + k],
                              W1[(2 * L + 1) * (DIN + DEDGE) + DIN + k]);
    }
    __syncthreads();

    const int L = threadIdx.x & 31;
    const int w = threadIdx.x >> 5;

    ull wp[DEDGE];
    #pragma unroll
    for (int k = 0; k < DEDGE; k++) {
        float2 t = sW[k * 32 + L];
        wp[k] = packf2(t.x, t.y);
    }
    const float aL = __ldg(&attn[2 * L]);
    const float aH = __ldg(&attn[2 * L + 1]);

    const int gwarp = blockIdx.x * 8 + w;        // 256 edges/block
    const int base  = gwarp * 32;

    const int s_own = src[base + L];     // coalesced
    const int d_own = dst[base + L];     // coalesced
    const float4* ea4 = (const float4*)edge_attr;

    // Phase A: partials
    #pragma unroll 2
    for (int i = 0; i < 32; i++) {
        const int e = base + i;
        const int s = __shfl_sync(0xFFFFFFFFu, s_own, i);

        float2 sf = *reinterpret_cast<const float2*>(&g_sf[s * DOUT + 2 * L]);
        ull f = packf2(sf.x, sf.y);

        #pragma unroll
        for (int g = 0; g < 4; g++) {
            float4 ev = __ldg(&ea4[e * 4 + g]);           // lane-uniform broadcast
            ffma2(f, wp[4 * g + 0], packf2(ev.x, ev.x));
            ffma2(f, wp[4 * g + 1], packf2(ev.y, ev.y));
            ffma2(f, wp[4 * g + 2], packf2(ev.z, ev.z));
            ffma2(f, wp[4 * g + 3], packf2(ev.w, ev.w));
        }

        float flo, fhi;
        unpackf2(f, flo, fhi);
        sP[w][i][L] = leaky(flo) * aL + leaky(fhi) * aH;
    }
    __syncwarp();

    // Phase B: lane L reduces its own edge (row L), conflict-free via pad 33
    float s0 = 0.f, s1 = 0.f, s2 = 0.f, s3 = 0.f;
    #pragma unroll
    for (int j = 0; j < 32; j += 4) {
        s0 += sP[w][L][j];
        s1 += sP[w][L][j + 1];
        s2 += sP[w][L][j + 2];
        s3 += sP[w][L][j + 3];
    }
    float logit = (s0 + s1) + (s2 + s3) + g_rdot[d_own];

    int pos = atomicAdd(&g_wptr[d_own], 1);               // spread-address
    g_ls[pos] = make_float2(logit, __int_as_float(s_own));
}

// ---------------- K5: warp-per-dst softmax + aggregation ----------------
__global__ __launch_bounds__(256) void k_aggregate(const float* __restrict__ bias,
                                                   float* __restrict__ out) {
    __shared__ float2 sA[8][32];          // [warp][idx] = {alpha, src-bits}

    const int lane = threadIdx.x & 31;
    const int w    = threadIdx.x >> 5;
    const int gw   = (blockIdx.x * blockDim.x + threadIdx.x) >> 5;
    if (gw >= NN) return;
    const int n = gw;

    int beg = g_rowptr[n];
    int end = g_rowptr[n + 1];
    int cnt = end - beg;

    float b0 = bias[2 * lane];
    float b1 = bias[2 * lane + 1];

    if (cnt == 0) {
        out[n * DOUT + 2 * lane]     = b0;
        out[n * DOUT + 2 * lane + 1] = b1;
        return;
    }

    float2 v = make_float2(-INFINITY, 0.0f);
    if (lane < cnt) v = g_ls[beg + lane];

    float lm = v.x;
    for (int j = beg + 32 + lane; j < end; j += 32)
        lm = fmaxf(lm, g_ls[j].x);
    float m = warp_max(lm);

    float le = (lane < cnt) ? __expf(v.x - m) : 0.0f;
    for (int j = beg + 32 + lane; j < end; j += 32)
        le += __expf(g_ls[j].x - m);
    float inv = 1.0f / warp_sum(le);

    sA[w][lane] = make_float2((lane < cnt) ? __expf(v.x - m) * inv : 0.0f, v.y);
    __syncwarp();

    float acc0 = 0.0f, acc1 = 0.0f;
    int lim = cnt < 32 ? cnt : 32;
    #pragma unroll 4
    for (int idx = 0; idx < lim; idx++) {
        float2 t = sA[w][idx];            // broadcast LDS.64
        int   s = __float_as_int(t.y);
        float a = t.x;
        float2 xv = *reinterpret_cast<const float2*>(&g_xt[s * DOUT + 2 * lane]);
        acc0 = fmaf(a, xv.x, acc0);
        acc1 = fmaf(a, xv.y, acc1);
    }
    for (int j = beg + 32; j < end; j++) {
        float2 lsv = g_ls[j];
        int   s = __float_as_int(lsv.y);
        float a = __expf(lsv.x - m) * inv;
        float2 xv = *reinterpret_cast<const float2*>(&g_xt[s * DOUT + 2 * lane]);
        acc0 = fmaf(a, xv.x, acc0);
        acc1 = fmaf(a, xv.y, acc1);
    }
    out[n * DOUT + 2 * lane]     = acc0 + b0;
    out[n * DOUT + 2 * lane + 1] = acc1 + b1;
}

// ---------------- launch: fork-join dual-stream (graph-capturable) ----------
extern "C" void kernel_launch(void* const* d_in, const int* in_sizes, int n_in,
                              void* d_out, int out_size) {
    const float* x         = (const float*)d_in[0];
    const float* edge_attr = (const float*)d_in[1];
    const int*   src       = (const int*)d_in[2];
    const int*   dst       = (const int*)d_in[3];
    const float* W1        = (const float*)d_in[4];
    const float* W2        = (const float*)d_in[5];
    const float* attn      = (const float*)d_in[6];
    const float* bias      = (const float*)d_in[7];
    float* out             = (float*)d_out;

    static cudaStream_t side = nullptr;
    static cudaEvent_t  evFork = nullptr, evJoin = nullptr;
    if (side == nullptr) {
        cudaStreamCreateWithFlags(&side, cudaStreamNonBlocking);
        cudaEventCreateWithFlags(&evFork, cudaEventDisableTiming);
        cudaEventCreateWithFlags(&evJoin, cudaEventDisableTiming);
    }

    void* count_ptr = nullptr;
    cudaGetSymbolAddress(&count_ptr, g_count);

    // fork: side stream runs the hist/scan chain concurrently with k_node
    cudaEventRecord(evFork, 0);
    cudaStreamWaitEvent(side, evFork, 0);

    cudaMemsetAsync(count_ptr, 0, NN * sizeof(int), side);
    k_hist<<<(EE / 4 + 255) / 256, 256, 0, side>>>(dst);
    k_scan1<<<SCAN_BLOCKS, SCAN_T, 0, side>>>();
    k_scan23<<<(NN + 255) / 256, 256, 0, side>>>();
    cudaEventRecord(evJoin, side);

    k_node<<<NODE_BLOCKS, 256>>>(x, W1, W2, attn);

    // join: logits needs both k_node outputs and wptr
    cudaStreamWaitEvent(0, evJoin, 0);
    k_logits<<<EE / 256, 256>>>(edge_attr, src, dst, W1, attn);
    k_aggregate<<<(NN * 32 + 255) / 256, 256>>>(bias, out);
}